// round 3
// baseline (speedup 1.0000x reference)
#include <cuda_runtime.h>
#include <math.h>

#define B_ 8
#define T_ 128
#define S_ 256
#define H_ 512

// Scratch (allocation-free rule: device globals)
__device__ float g_qs[B_ * T_ * H_];          // 2 MB
__device__ float g_hs[B_ * S_ * H_];          // 4 MB
__device__ float g_ctx[B_ * T_ * H_];         // 2 MB
__device__ float g_part[2 * B_ * T_ * H_];    // 4 MB (split-K partials)

typedef unsigned long long u64;

__device__ __forceinline__ void ffma2(u64& d, u64 a, u64 b) {
    asm("fma.rn.f32x2 %0, %1, %2, %3;" : "=l"(d) : "l"(a), "l"(b), "l"(d));
}
__device__ __forceinline__ float2 unpk(u64 v) {
    float2 r;
    asm("mov.b64 {%0, %1}, %2;" : "=f"(r.x), "=f"(r.y) : "l"(v));
    return r;
}

// ---------------------------------------------------------------------------
// 64x64 tile fp32x2 GEMM core, K=512 fixed, C row stride 512.
// C[m,n] = sum_k A[m*lda + k] * Bw[n*ldb + k]
// 256 threads, microtile 4(m)x4(n) as 2 m-pairs (f32x2) x 4 n.
// Double-buffered smem, register-staged global prefetch.
// B stored duplicated ({b,b}) in smem so FFMA2 needs no packing.
// ---------------------------------------------------------------------------
__device__ __forceinline__ void gemm_tile64(
    const float* __restrict__ A, int lda,
    const float* __restrict__ Bw, int ldb,
    float* __restrict__ C, int m0, int n0)
{
    __shared__ float As[2][16][64];     // [buf][k][m]
    __shared__ float Bsd[2][16][128];   // [buf][k][2n] duplicated pairs

    const int tid = threadIdx.x;
    const int tx = tid & 15;            // n quad
    const int ty = tid >> 4;            // m quad
    const int lr = tid >> 2;            // 0..63 load row
    const int lc = (tid & 3) << 2;      // 0,4,8,12 load k offset

    const float* Ag = A + (size_t)(m0 + lr) * lda + lc;
    const float* Bg = Bw + (size_t)(n0 + lr) * ldb + lc;

    u64 acc[2][4];
    #pragma unroll
    for (int i = 0; i < 2; i++)
        #pragma unroll
        for (int j = 0; j < 4; j++) acc[i][j] = 0ull;  // {+0f,+0f}

    // preload tile 0
    float4 av = *reinterpret_cast<const float4*>(Ag);
    float4 bv = *reinterpret_cast<const float4*>(Bg);
    {
        As[0][lc + 0][lr] = av.x; As[0][lc + 1][lr] = av.y;
        As[0][lc + 2][lr] = av.z; As[0][lc + 3][lr] = av.w;
        float2* bd = reinterpret_cast<float2*>(&Bsd[0][0][0]);
        // Bsd[0][lc+i][2*lr] as float2
        bd[(lc + 0) * 64 + lr] = make_float2(bv.x, bv.x);
        bd[(lc + 1) * 64 + lr] = make_float2(bv.y, bv.y);
        bd[(lc + 2) * 64 + lr] = make_float2(bv.z, bv.z);
        bd[(lc + 3) * 64 + lr] = make_float2(bv.w, bv.w);
    }

    int cur = 0;
    #pragma unroll 1
    for (int it = 0; it < 32; ++it) {
        __syncthreads();   // current buffer ready

        // prefetch next global tile (registers)
        if (it + 1 < 32) {
            av = *reinterpret_cast<const float4*>(Ag + (it + 1) * 16);
            bv = *reinterpret_cast<const float4*>(Bg + (it + 1) * 16);
        }

        const float* Asc = &As[cur][0][0];
        const float* Bsc = &Bsd[cur][0][0];

        #pragma unroll
        for (int kq = 0; kq < 16; ++kq) {
            const ulonglong2 a2 =
                *reinterpret_cast<const ulonglong2*>(Asc + kq * 64 + ty * 4);
            const ulonglong2 b0 =
                *reinterpret_cast<const ulonglong2*>(Bsc + kq * 128 + tx * 8);
            const ulonglong2 b1 =
                *reinterpret_cast<const ulonglong2*>(Bsc + kq * 128 + tx * 8 + 4);
            ffma2(acc[0][0], a2.x, b0.x);
            ffma2(acc[0][1], a2.x, b0.y);
            ffma2(acc[0][2], a2.x, b1.x);
            ffma2(acc[0][3], a2.x, b1.y);
            ffma2(acc[1][0], a2.y, b0.x);
            ffma2(acc[1][1], a2.y, b0.y);
            ffma2(acc[1][2], a2.y, b1.x);
            ffma2(acc[1][3], a2.y, b1.y);
        }

        // stage next tile into the other buffer
        if (it + 1 < 32) {
            const int nb = cur ^ 1;
            As[nb][lc + 0][lr] = av.x; As[nb][lc + 1][lr] = av.y;
            As[nb][lc + 2][lr] = av.z; As[nb][lc + 3][lr] = av.w;
            float2* bd = reinterpret_cast<float2*>(&Bsd[nb][0][0]);
            bd[(lc + 0) * 64 + lr] = make_float2(bv.x, bv.x);
            bd[(lc + 1) * 64 + lr] = make_float2(bv.y, bv.y);
            bd[(lc + 2) * 64 + lr] = make_float2(bv.z, bv.z);
            bd[(lc + 3) * 64 + lr] = make_float2(bv.w, bv.w);
        }
        cur ^= 1;
    }

    // epilogue: rows 4ty+2mp+{0,1}, cols n0+4tx..+3
    #pragma unroll
    for (int mp = 0; mp < 2; mp++) {
        const float2 c0 = unpk(acc[mp][0]);
        const float2 c1 = unpk(acc[mp][1]);
        const float2 c2 = unpk(acc[mp][2]);
        const float2 c3 = unpk(acc[mp][3]);
        const int rl = m0 + ty * 4 + mp * 2;
        float4 lo4 = make_float4(c0.x, c1.x, c2.x, c3.x);
        float4 hi4 = make_float4(c0.y, c1.y, c2.y, c3.y);
        *reinterpret_cast<float4*>(&C[(size_t)rl * 512 + n0 + tx * 4]) = lo4;
        *reinterpret_cast<float4*>(&C[(size_t)(rl + 1) * 512 + n0 + tx * 4]) = hi4;
    }
}

// proj: grid (8, 48). y<16 -> qs = query@W_s^T (M=1024); else hs = enc@W_h^T (M=2048)
__global__ void __launch_bounds__(256, 2) proj_kernel(
    const float* __restrict__ query, const float* __restrict__ enc,
    const float* __restrict__ W_s, const float* __restrict__ W_h)
{
    const int by = blockIdx.y;
    const int n0 = blockIdx.x * 64;
    if (by < 16) {
        gemm_tile64(query, H_, W_s, H_, g_qs, by * 64, n0);
    } else {
        gemm_tile64(enc, H_, W_h, H_, g_hs, (by - 16) * 64, n0);
    }
}

// out gemm split-K: grid (8, 16, 2). z=0: ctx @ W_out[:, :512]; z=1: query @ W_out[:, 512:]
__global__ void __launch_bounds__(256, 2) outgemm_kernel(
    const float* __restrict__ query, const float* __restrict__ W_out)
{
    const int z = blockIdx.z;
    const float* A = z ? query : g_ctx;
    gemm_tile64(A, H_, W_out + z * H_, 2 * H_,
                g_part + (size_t)z * (B_ * T_ * H_),
                blockIdx.y * 64, blockIdx.x * 64);
}

// reduce: out = tanh(p0 + p1 + bias)
__global__ void __launch_bounds__(256) reduce_kernel(
    const float* __restrict__ bias, float* __restrict__ out)
{
    const int i = (blockIdx.x * 256 + threadIdx.x) * 4;
    const float4 p0 = *reinterpret_cast<const float4*>(&g_part[i]);
    const float4 p1 = *reinterpret_cast<const float4*>(&g_part[B_ * T_ * H_ + i]);
    const float4 bb = *reinterpret_cast<const float4*>(&bias[i & (H_ - 1)]);
    float4 o;
    o.x = tanhf(p0.x + p1.x + bb.x);
    o.y = tanhf(p0.y + p1.y + bb.y);
    o.z = tanhf(p0.z + p1.z + bb.z);
    o.w = tanhf(p0.w + p1.w + bb.w);
    *reinterpret_cast<float4*>(&out[i]) = o;
}

// ---------------------------------------------------------------------------
// Fused attention (unchanged structure; tanh.approx = 1 MUFU per element)
// ---------------------------------------------------------------------------
#define TT 4    // t rows per block
#define SC 16   // s rows per smem chunk

__global__ void __launch_bounds__(256) attn_kernel(
    const float* __restrict__ qs, const float* __restrict__ hs,
    const float* __restrict__ enc, const float* __restrict__ v,
    const int* __restrict__ lens, float* __restrict__ ctx)
{
    __shared__ float sh_hs[SC * H_];          // 32 KB (reused for pass-2 combine)
    __shared__ float sh_sc[TT][S_];           // 4 KB
    __shared__ float sh_rsum[TT];

    const int b    = blockIdx.y;
    const int t0   = blockIdx.x * TT;
    const int tid  = threadIdx.x;
    const int lane = tid & 31;
    const int wid  = tid >> 5;
    const int t_loc = wid >> 1;
    const int shalf = wid & 1;

    // Preload q row + v into registers (h = lane + 32*j)
    float qreg[16], vreg[16];
    {
        const float* qrow = qs + (size_t)(b * T_ + t0 + t_loc) * H_;
        #pragma unroll
        for (int j = 0; j < 16; j++) {
            qreg[j] = qrow[lane + 32 * j];
            vreg[j] = v[lane + 32 * j];
        }
    }

    const float* hsb  = hs  + (size_t)b * S_ * H_;
    const float* encb = enc + (size_t)b * S_ * H_;

    // ---- Pass 1: scores ----
    for (int s0 = 0; s0 < S_; s0 += SC) {
        #pragma unroll
        for (int r = 0; r < (SC * H_) / (256 * 4); r++) {
            const int off = (r * 256 + tid) * 4;
            *reinterpret_cast<float4*>(&sh_hs[off]) =
                *reinterpret_cast<const float4*>(&hsb[(size_t)s0 * H_ + off]);
        }
        __syncthreads();

        #pragma unroll
        for (int i = 0; i < SC / 2; i++) {
            const int sl = shalf * (SC / 2) + i;
            const float* hrow = &sh_hs[sl * H_];
            float acc = 0.f;
            #pragma unroll
            for (int j = 0; j < 16; j++) {
                const float x = qreg[j] + hrow[lane + 32 * j];
                float th;
                asm("tanh.approx.f32 %0, %1;" : "=f"(th) : "f"(x));
                acc = fmaf(th, vreg[j], acc);
            }
            acc += __shfl_xor_sync(0xffffffffu, acc, 16);
            acc += __shfl_xor_sync(0xffffffffu, acc, 8);
            acc += __shfl_xor_sync(0xffffffffu, acc, 4);
            acc += __shfl_xor_sync(0xffffffffu, acc, 2);
            acc += __shfl_xor_sync(0xffffffffu, acc, 1);
            if (lane == 0) sh_sc[t_loc][s0 + sl] = acc;
        }
        __syncthreads();
    }

    // ---- Softmax (warp per t row) ----
    const int len = lens[b];
    if (wid < TT) {
        const int t = wid;
        float vals[S_ / 32];
        float m = -1e30f;
        #pragma unroll
        for (int i = 0; i < S_ / 32; i++) {
            const int s = lane + 32 * i;
            const float sc = (s < len) ? sh_sc[t][s] : -1e30f;
            vals[i] = sc;
            m = fmaxf(m, sc);
        }
        #pragma unroll
        for (int o = 16; o; o >>= 1) m = fmaxf(m, __shfl_xor_sync(0xffffffffu, m, o));
        float sum = 0.f;
        #pragma unroll
        for (int i = 0; i < S_ / 32; i++) {
            const int s = lane + 32 * i;
            const float e = (s < len) ? __expf(vals[i] - m) : 0.f;
            sh_sc[t][s] = e;
            sum += e;
        }
        #pragma unroll
        for (int o = 16; o; o >>= 1) sum += __shfl_xor_sync(0xffffffffu, sum, o);
        if (lane == 0) sh_rsum[t] = 1.0f / sum;
    }
    __syncthreads();

    // ---- Pass 2: context = attn @ enc ----
    const int g  = tid >> 7;
    const int c4 = tid & 127;
    float4 acc4[TT];
    #pragma unroll
    for (int t = 0; t < TT; t++) acc4[t] = make_float4(0.f, 0.f, 0.f, 0.f);

    const int sbeg = g * (S_ / 2);
    #pragma unroll 4
    for (int s = sbeg; s < sbeg + S_ / 2; s++) {
        const float4 e4 = *reinterpret_cast<const float4*>(&encb[(size_t)s * H_ + c4 * 4]);
        #pragma unroll
        for (int t = 0; t < TT; t++) {
            const float w = sh_sc[t][s];
            acc4[t].x = fmaf(w, e4.x, acc4[t].x);
            acc4[t].y = fmaf(w, e4.y, acc4[t].y);
            acc4[t].z = fmaf(w, e4.z, acc4[t].z);
            acc4[t].w = fmaf(w, e4.w, acc4[t].w);
        }
    }

    if (g == 0) {
        #pragma unroll
        for (int t = 0; t < TT; t++)
            *reinterpret_cast<float4*>(&sh_hs[(t * 128 + c4) * 4]) = acc4[t];
    }
    __syncthreads();
    if (g == 1) {
        #pragma unroll
        for (int t = 0; t < TT; t++) {
            float4 o = *reinterpret_cast<const float4*>(&sh_hs[(t * 128 + c4) * 4]);
            const float rs = sh_rsum[t];
            o.x = (o.x + acc4[t].x) * rs;
            o.y = (o.y + acc4[t].y) * rs;
            o.z = (o.z + acc4[t].z) * rs;
            o.w = (o.w + acc4[t].w) * rs;
            *reinterpret_cast<float4*>(&ctx[(size_t)(b * T_ + t0 + t) * H_ + c4 * 4]) = o;
        }
    }
}

// ---------------------------------------------------------------------------
extern "C" void kernel_launch(void* const* d_in, const int* in_sizes, int n_in,
                              void* d_out, int out_size)
{
    const float* query = (const float*)d_in[0];  // (B,T,H)
    const float* enc   = (const float*)d_in[1];  // (B,S,H)
    const int*   lens  = (const int*)d_in[2];    // (B,)
    const float* W_s   = (const float*)d_in[3];  // (H,H)
    const float* W_h   = (const float*)d_in[4];  // (H,H)
    const float* v     = (const float*)d_in[5];  // (H,)
    const float* W_out = (const float*)d_in[6];  // (H,2H)
    const float* b_out = (const float*)d_in[7];  // (H,)
    float* out = (float*)d_out;                  // (B,T,H)

    float *qs = nullptr, *hsp = nullptr, *ctx = nullptr;
    cudaGetSymbolAddress((void**)&qs,  g_qs);
    cudaGetSymbolAddress((void**)&hsp, g_hs);
    cudaGetSymbolAddress((void**)&ctx, g_ctx);

    // qs + hs in one launch (384 blocks)
    proj_kernel<<<dim3(8, 48), 256>>>(query, enc, W_s, W_h);
    // fused scores/softmax/context
    attn_kernel<<<dim3(T_ / TT, B_), 256>>>(qs, hsp, enc, v, lens, ctx);
    // out partials, split-K at the concat boundary (256 blocks)
    outgemm_kernel<<<dim3(8, 16, 2), 256>>>(query, W_out);
    // out = tanh(p0 + p1 + bias)
    reduce_kernel<<<dim3((B_ * T_ * H_) / (256 * 4)), 256>>>(b_out, out);
}

// round 5
// speedup vs baseline: 2.2748x; 2.2748x over previous
#include <cuda_runtime.h>
#include <cuda_bf16.h>
#include <mma.h>
#include <math.h>
#include <stdint.h>

using namespace nvcuda;

#define B_ 8
#define T_ 128
#define S_ 256
#define H_ 512

// Scratch (allocation-free rule: device globals)
__device__ float g_qs[B_ * T_ * H_];    // 2 MB
__device__ float g_hs[B_ * S_ * H_];    // 4 MB
__device__ float g_ctx[B_ * T_ * H_];   // 2 MB

// ---------------------------------------------------------------------------
// bf16 hi/lo split: x ~= hi + lo, error ~2^-17 relative
// ---------------------------------------------------------------------------
__device__ __forceinline__ void bsplit(float x, __nv_bfloat16& hi, __nv_bfloat16& lo) {
    hi = __float2bfloat16(x);
    lo = __float2bfloat16(x - __bfloat162float(hi));
}

// smem layout (bytes): bf16 tiles 64 rows x 32 k, pitch 40 elements (80 B)
#define PITCH 40
#define TILE_B (64 * PITCH * 2)      // 5120 B per tile
#define AHI_OFF 0
#define ALO_OFF (TILE_B)
#define BHI_OFF (2 * TILE_B)
#define BLO_OFF (3 * TILE_B)
#define SMEM_BYTES (4 * TILE_B)      // 20480 B (also reused as fp32 staging)

// ---------------------------------------------------------------------------
// Tensor-core GEMM via wmma bf16 + error compensation (3 products).
// C[m,n] = sum_k A[m,k] * Bw[n*ldb + k];  A rows are 512 floats wide.
// CONCAT: A row = [A | A2] split at k=512 (each source pitch 512).
// OUTMODE: epilogue tanh(x + bias[n]).
// Block: 128 threads (4 warps), tile 64(M)x64(N), K-chunk 32.
// ---------------------------------------------------------------------------
template <bool OUTMODE, bool CONCAT>
__device__ __forceinline__ void gemm_wmma(
    char* smem,
    const float* __restrict__ A, const float* __restrict__ A2,
    const float* __restrict__ Bw, int ldb,
    const float* __restrict__ bias, float* __restrict__ C,
    int m0, int n0, int Ktot)
{
    const int tid  = threadIdx.x;
    const int wid  = tid >> 5;
    const int lane = tid & 31;
    const int m0w  = (wid >> 1) * 32;   // warp tile origin in block tile
    const int n0w  = (wid & 1) * 32;

    __nv_bfloat16* sAhi = reinterpret_cast<__nv_bfloat16*>(smem + AHI_OFF);
    __nv_bfloat16* sAlo = reinterpret_cast<__nv_bfloat16*>(smem + ALO_OFF);
    __nv_bfloat16* sBhi = reinterpret_cast<__nv_bfloat16*>(smem + BHI_OFF);
    __nv_bfloat16* sBlo = reinterpret_cast<__nv_bfloat16*>(smem + BLO_OFF);

    wmma::fragment<wmma::accumulator, 16, 16, 16, float> acc[2][2];
    #pragma unroll
    for (int mi = 0; mi < 2; mi++)
        #pragma unroll
        for (int ni = 0; ni < 2; ni++)
            wmma::fill_fragment(acc[mi][ni], 0.0f);

    const int nchunks = Ktot / 32;
    #pragma unroll 1
    for (int it = 0; it < nchunks; ++it) {
        const int k0 = it * 32;

        // ---- gmem -> regs (4 float4 for A, 4 for B per thread) ----
        const float* Asrc = A;
        int koff = k0;
        if (CONCAT && k0 >= H_) { Asrc = A2; koff = k0 - H_; }

        float4 a4[4], b4[4];
        #pragma unroll
        for (int i = 0; i < 4; i++) {
            const int idx = i * 128 + tid;       // 0..511
            const int row = idx >> 3, c4 = idx & 7;
            a4[i] = *reinterpret_cast<const float4*>(
                Asrc + (size_t)(m0 + row) * H_ + koff + c4 * 4);
            b4[i] = *reinterpret_cast<const float4*>(
                Bw + (size_t)(n0 + row) * ldb + k0 + c4 * 4);
        }

        __syncthreads();   // previous chunk's MMAs done

        // ---- split + store to smem ----
        #pragma unroll
        for (int i = 0; i < 4; i++) {
            const int idx = i * 128 + tid;
            const int row = idx >> 3, c4 = idx & 7;
            const int off = row * PITCH + c4 * 4;
            union { __nv_bfloat16 h[4]; uint2 u; } ph, pl;
            bsplit(a4[i].x, ph.h[0], pl.h[0]); bsplit(a4[i].y, ph.h[1], pl.h[1]);
            bsplit(a4[i].z, ph.h[2], pl.h[2]); bsplit(a4[i].w, ph.h[3], pl.h[3]);
            *reinterpret_cast<uint2*>(&sAhi[off]) = ph.u;
            *reinterpret_cast<uint2*>(&sAlo[off]) = pl.u;
            bsplit(b4[i].x, ph.h[0], pl.h[0]); bsplit(b4[i].y, ph.h[1], pl.h[1]);
            bsplit(b4[i].z, ph.h[2], pl.h[2]); bsplit(b4[i].w, ph.h[3], pl.h[3]);
            *reinterpret_cast<uint2*>(&sBhi[off]) = ph.u;
            *reinterpret_cast<uint2*>(&sBlo[off]) = pl.u;
        }
        __syncthreads();

        // ---- MMAs: 2 k-frags x (2x2 tiles) x 3 products ----
        #pragma unroll
        for (int kf = 0; kf < 2; kf++) {
            const int ko = kf * 16;
            wmma::fragment<wmma::matrix_a, 16, 16, 16, __nv_bfloat16, wmma::row_major> ahi[2], alo[2];
            wmma::fragment<wmma::matrix_b, 16, 16, 16, __nv_bfloat16, wmma::col_major> bhi[2], blo[2];
            #pragma unroll
            for (int mi = 0; mi < 2; mi++) {
                wmma::load_matrix_sync(ahi[mi], &sAhi[(m0w + 16 * mi) * PITCH + ko], PITCH);
                wmma::load_matrix_sync(alo[mi], &sAlo[(m0w + 16 * mi) * PITCH + ko], PITCH);
            }
            #pragma unroll
            for (int ni = 0; ni < 2; ni++) {
                wmma::load_matrix_sync(bhi[ni], &sBhi[(n0w + 16 * ni) * PITCH + ko], PITCH);
                wmma::load_matrix_sync(blo[ni], &sBlo[(n0w + 16 * ni) * PITCH + ko], PITCH);
            }
            #pragma unroll
            for (int mi = 0; mi < 2; mi++)
                #pragma unroll
                for (int ni = 0; ni < 2; ni++) {
                    wmma::mma_sync(acc[mi][ni], ahi[mi], bhi[ni], acc[mi][ni]);
                    wmma::mma_sync(acc[mi][ni], ahi[mi], blo[ni], acc[mi][ni]);
                    wmma::mma_sync(acc[mi][ni], alo[mi], bhi[ni], acc[mi][ni]);
                }
        }
    }

    if (!OUTMODE) {
        // direct store to C (pitch 512)
        #pragma unroll
        for (int mi = 0; mi < 2; mi++)
            #pragma unroll
            for (int ni = 0; ni < 2; ni++)
                wmma::store_matrix_sync(
                    &C[(size_t)(m0 + m0w + 16 * mi) * H_ + n0 + n0w + 16 * ni],
                    acc[mi][ni], H_, wmma::mem_row_major);
    } else {
        // stage 32x32 per warp in smem, then tanh(x + bias)
        __syncthreads();
        float* stage = reinterpret_cast<float*>(smem) + wid * 32 * 36;
        #pragma unroll
        for (int mi = 0; mi < 2; mi++)
            #pragma unroll
            for (int ni = 0; ni < 2; ni++)
                wmma::store_matrix_sync(&stage[(16 * mi) * 36 + 16 * ni],
                                        acc[mi][ni], 36, wmma::mem_row_major);
        __syncwarp();
        const int m = m0 + m0w + lane;
        float* Crow = C + (size_t)m * H_ + n0 + n0w;
        #pragma unroll
        for (int q = 0; q < 8; q++) {
            const float4 s = *reinterpret_cast<const float4*>(&stage[lane * 36 + q * 4]);
            const float4 bb = *reinterpret_cast<const float4*>(&bias[n0 + n0w + q * 4]);
            float4 o;
            o.x = tanhf(s.x + bb.x); o.y = tanhf(s.y + bb.y);
            o.z = tanhf(s.z + bb.z); o.w = tanhf(s.w + bb.w);
            *reinterpret_cast<float4*>(Crow + q * 4) = o;
        }
    }
}

// proj: grid (8, 48). y<16 -> qs = query@W_s^T (M=1024); else hs = enc@W_h^T (M=2048)
__global__ void __launch_bounds__(128) proj_wmma(
    const float* __restrict__ query, const float* __restrict__ enc,
    const float* __restrict__ W_s, const float* __restrict__ W_h)
{
    __shared__ __align__(16) char smem[SMEM_BYTES];
    const int n0 = blockIdx.x * 64;
    const int my = blockIdx.y;
    if (my < 16)
        gemm_wmma<false, false>(smem, query, nullptr, W_s, H_, nullptr, g_qs,
                                my * 64, n0, H_);
    else
        gemm_wmma<false, false>(smem, enc, nullptr, W_h, H_, nullptr, g_hs,
                                (my - 16) * 64, n0, H_);
}

// out: grid (8, 16). out = tanh([ctx|query] @ W_out^T + b), K=1024
__global__ void __launch_bounds__(128) out_wmma(
    const float* __restrict__ query, const float* __restrict__ W_out,
    const float* __restrict__ b_out, float* __restrict__ out)
{
    __shared__ __align__(16) char smem[SMEM_BYTES];
    gemm_wmma<true, true>(smem, g_ctx, query, W_out, 2 * H_, b_out, out,
                          blockIdx.y * 64, blockIdx.x * 64, 2 * H_);
}

// ---------------------------------------------------------------------------
// Fused attention (unchanged: tanh.approx, validated rel_err 2.8e-7)
// ---------------------------------------------------------------------------
#define TT 4
#define SC 16

__global__ void __launch_bounds__(256) attn_kernel(
    const float* __restrict__ qs, const float* __restrict__ hs,
    const float* __restrict__ enc, const float* __restrict__ v,
    const int* __restrict__ lens, float* __restrict__ ctx)
{
    __shared__ float sh_hs[SC * H_];
    __shared__ float sh_sc[TT][S_];
    __shared__ float sh_rsum[TT];

    const int b    = blockIdx.y;
    const int t0   = blockIdx.x * TT;
    const int tid  = threadIdx.x;
    const int lane = tid & 31;
    const int wid  = tid >> 5;
    const int t_loc = wid >> 1;
    const int shalf = wid & 1;

    float qreg[16], vreg[16];
    {
        const float* qrow = qs + (size_t)(b * T_ + t0 + t_loc) * H_;
        #pragma unroll
        for (int j = 0; j < 16; j++) {
            qreg[j] = qrow[lane + 32 * j];
            vreg[j] = v[lane + 32 * j];
        }
    }

    const float* hsb  = hs  + (size_t)b * S_ * H_;
    const float* encb = enc + (size_t)b * S_ * H_;

    for (int s0 = 0; s0 < S_; s0 += SC) {
        #pragma unroll
        for (int r = 0; r < (SC * H_) / (256 * 4); r++) {
            const int off = (r * 256 + tid) * 4;
            *reinterpret_cast<float4*>(&sh_hs[off]) =
                *reinterpret_cast<const float4*>(&hsb[(size_t)s0 * H_ + off]);
        }
        __syncthreads();

        #pragma unroll
        for (int i = 0; i < SC / 2; i++) {
            const int sl = shalf * (SC / 2) + i;
            const float* hrow = &sh_hs[sl * H_];
            float acc = 0.f;
            #pragma unroll
            for (int j = 0; j < 16; j++) {
                const float x = qreg[j] + hrow[lane + 32 * j];
                float th;
                asm("tanh.approx.f32 %0, %1;" : "=f"(th) : "f"(x));
                acc = fmaf(th, vreg[j], acc);
            }
            acc += __shfl_xor_sync(0xffffffffu, acc, 16);
            acc += __shfl_xor_sync(0xffffffffu, acc, 8);
            acc += __shfl_xor_sync(0xffffffffu, acc, 4);
            acc += __shfl_xor_sync(0xffffffffu, acc, 2);
            acc += __shfl_xor_sync(0xffffffffu, acc, 1);
            if (lane == 0) sh_sc[t_loc][s0 + sl] = acc;
        }
        __syncthreads();
    }

    const int len = lens[b];
    if (wid < TT) {
        const int t = wid;
        float vals[S_ / 32];
        float m = -1e30f;
        #pragma unroll
        for (int i = 0; i < S_ / 32; i++) {
            const int s = lane + 32 * i;
            const float sc = (s < len) ? sh_sc[t][s] : -1e30f;
            vals[i] = sc;
            m = fmaxf(m, sc);
        }
        #pragma unroll
        for (int o = 16; o; o >>= 1) m = fmaxf(m, __shfl_xor_sync(0xffffffffu, m, o));
        float sum = 0.f;
        #pragma unroll
        for (int i = 0; i < S_ / 32; i++) {
            const int s = lane + 32 * i;
            const float e = (s < len) ? __expf(vals[i] - m) : 0.f;
            sh_sc[t][s] = e;
            sum += e;
        }
        #pragma unroll
        for (int o = 16; o; o >>= 1) sum += __shfl_xor_sync(0xffffffffu, sum, o);
        if (lane == 0) sh_rsum[t] = 1.0f / sum;
    }
    __syncthreads();

    const int g  = tid >> 7;
    const int c4 = tid & 127;
    float4 acc4[TT];
    #pragma unroll
    for (int t = 0; t < TT; t++) acc4[t] = make_float4(0.f, 0.f, 0.f, 0.f);

    const int sbeg = g * (S_ / 2);
    #pragma unroll 4
    for (int s = sbeg; s < sbeg + S_ / 2; s++) {
        const float4 e4 = *reinterpret_cast<const float4*>(&encb[(size_t)s * H_ + c4 * 4]);
        #pragma unroll
        for (int t = 0; t < TT; t++) {
            const float w = sh_sc[t][s];
            acc4[t].x = fmaf(w, e4.x, acc4[t].x);
            acc4[t].y = fmaf(w, e4.y, acc4[t].y);
            acc4[t].z = fmaf(w, e4.z, acc4[t].z);
            acc4[t].w = fmaf(w, e4.w, acc4[t].w);
        }
    }

    if (g == 0) {
        #pragma unroll
        for (int t = 0; t < TT; t++)
            *reinterpret_cast<float4*>(&sh_hs[(t * 128 + c4) * 4]) = acc4[t];
    }
    __syncthreads();
    if (g == 1) {
        #pragma unroll
        for (int t = 0; t < TT; t++) {
            float4 o = *reinterpret_cast<const float4*>(&sh_hs[(t * 128 + c4) * 4]);
            const float rs = sh_rsum[t];
            o.x = (o.x + acc4[t].x) * rs;
            o.y = (o.y + acc4[t].y) * rs;
            o.z = (o.z + acc4[t].z) * rs;
            o.w = (o.w + acc4[t].w) * rs;
            *reinterpret_cast<float4*>(&ctx[(size_t)(b * T_ + t0 + t) * H_ + c4 * 4]) = o;
        }
    }
}

// ---------------------------------------------------------------------------
extern "C" void kernel_launch(void* const* d_in, const int* in_sizes, int n_in,
                              void* d_out, int out_size)
{
    const float* query = (const float*)d_in[0];
    const float* enc   = (const float*)d_in[1];
    const int*   lens  = (const int*)d_in[2];
    const float* W_s   = (const float*)d_in[3];
    const float* W_h   = (const float*)d_in[4];
    const float* v     = (const float*)d_in[5];
    const float* W_out = (const float*)d_in[6];
    const float* b_out = (const float*)d_in[7];
    float* out = (float*)d_out;

    float *qs = nullptr, *hsp = nullptr, *ctx = nullptr;
    cudaGetSymbolAddress((void**)&qs,  g_qs);
    cudaGetSymbolAddress((void**)&hsp, g_hs);
    cudaGetSymbolAddress((void**)&ctx, g_ctx);

    // qs + hs (384 CTAs, tensor pipe via wmma bf16x2)
    proj_wmma<<<dim3(8, 48), 128>>>(query, enc, W_s, W_h);
    // fused scores/softmax/context
    attn_kernel<<<dim3(T_ / TT, B_), 256>>>(qs, hsp, enc, v, lens, ctx);
    // out = tanh([ctx|query] @ W_out^T + b)  (128 CTAs, K=1024)
    out_wmma<<<dim3(8, 16), 128>>>(query, W_out, b_out, out);
}

// round 6
// speedup vs baseline: 2.4250x; 1.0660x over previous
#include <cuda_runtime.h>
#include <cuda_bf16.h>
#include <mma.h>
#include <math.h>
#include <stdint.h>

using namespace nvcuda;

#define B_ 8
#define T_ 128
#define S_ 256
#define H_ 512

// fp32 scratch
__device__ float g_qs[B_ * T_ * H_];
__device__ float g_hs[B_ * S_ * H_];
// bf16 hi/lo pre-split operands
__device__ __nv_bfloat16 g_qhi[B_ * T_ * H_],  g_qlo[B_ * T_ * H_];
__device__ __nv_bfloat16 g_ehi[B_ * S_ * H_],  g_elo[B_ * S_ * H_];
__device__ __nv_bfloat16 g_wshi[H_ * H_],      g_wslo[H_ * H_];
__device__ __nv_bfloat16 g_whhi[H_ * H_],      g_whlo[H_ * H_];
__device__ __nv_bfloat16 g_wohi[H_ * 2 * H_],  g_wolo[H_ * 2 * H_];
__device__ __nv_bfloat16 g_chi[B_ * T_ * H_],  g_clo[B_ * T_ * H_];

// ---------------------------------------------------------------------------
__device__ __forceinline__ void bsplit(float x, __nv_bfloat16& hi, __nv_bfloat16& lo) {
    hi = __float2bfloat16(x);
    lo = __float2bfloat16(x - __bfloat162float(hi));
}
__device__ __forceinline__ uint32_t smem_u32(const void* p) {
    uint32_t a;
    asm("{ .reg .u64 t; cvta.to.shared.u64 t, %1; cvt.u32.u64 %0, t; }"
        : "=r"(a) : "l"(p));
    return a;
}
__device__ __forceinline__ void cpa16(uint32_t d, const void* s) {
    asm volatile("cp.async.cg.shared.global [%0], [%1], 16;" :: "r"(d), "l"(s));
}
#define CP_COMMIT() asm volatile("cp.async.commit_group;" ::: "memory")
#define CP_WAIT1()  asm volatile("cp.async.wait_group 1;" ::: "memory")
#define CP_WAIT0()  asm volatile("cp.async.wait_group 0;" ::: "memory")

// ---------------------------------------------------------------------------
// convert: split inputs + weights into bf16 hi/lo (one float4 per thread)
// segments (float4 units): q 131072 | enc 262144 | ws 65536 | wh 65536 | wout 131072
// ---------------------------------------------------------------------------
__global__ void __launch_bounds__(256) convert_kernel(
    const float* __restrict__ query, const float* __restrict__ enc,
    const float* __restrict__ W_s, const float* __restrict__ W_h,
    const float* __restrict__ W_out)
{
    const int i4 = blockIdx.x * 256 + threadIdx.x;
    const float* src;
    __nv_bfloat16 *dhi, *dlo;
    int off;
    if (i4 < 131072)      { src = query; dhi = g_qhi;  dlo = g_qlo;  off = i4; }
    else if (i4 < 393216) { src = enc;   dhi = g_ehi;  dlo = g_elo;  off = i4 - 131072; }
    else if (i4 < 458752) { src = W_s;   dhi = g_wshi; dlo = g_wslo; off = i4 - 393216; }
    else if (i4 < 524288) { src = W_h;   dhi = g_whhi; dlo = g_whlo; off = i4 - 458752; }
    else                  { src = W_out; dhi = g_wohi; dlo = g_wolo; off = i4 - 524288; }

    const float4 v = reinterpret_cast<const float4*>(src)[off];
    union { __nv_bfloat16 h[4]; uint2 u; } ph, pl;
    bsplit(v.x, ph.h[0], pl.h[0]); bsplit(v.y, ph.h[1], pl.h[1]);
    bsplit(v.z, ph.h[2], pl.h[2]); bsplit(v.w, ph.h[3], pl.h[3]);
    reinterpret_cast<uint2*>(dhi)[off] = ph.u;
    reinterpret_cast<uint2*>(dlo)[off] = pl.u;
}

// ---------------------------------------------------------------------------
// cp.async double-buffered wmma GEMM (bf16 3-term compensation).
// C[m,n] = sum_k A[m,k] * Bw[n*ldb + k];  A pitch H_, CONCAT splits at k=512.
// Tile 64x64, 128 threads, K-chunk 32.
// ---------------------------------------------------------------------------
#define PITCH 40
#define TILE_B (64 * PITCH * 2)          // 5120 B
#define AHI_O 0
#define ALO_O (TILE_B)
#define BHI_O (2 * TILE_B)
#define BLO_O (3 * TILE_B)
#define BUF_B (4 * TILE_B)               // 20480 B per stage
#define SMEM_BYTES (2 * BUF_B)           // 40960 B

template <bool CONCAT>
__device__ __forceinline__ void issue_chunk(
    uint32_t sb,
    const __nv_bfloat16* __restrict__ Ahi, const __nv_bfloat16* __restrict__ Alo,
    const __nv_bfloat16* __restrict__ A2hi, const __nv_bfloat16* __restrict__ A2lo,
    const __nv_bfloat16* __restrict__ Bhi, const __nv_bfloat16* __restrict__ Blo,
    int ldb, int m0, int n0, int k0, int tid)
{
    const __nv_bfloat16* ah = Ahi;
    const __nv_bfloat16* al = Alo;
    int koff = k0;
    if (CONCAT && k0 >= H_) { ah = A2hi; al = A2lo; koff = k0 - H_; }
    #pragma unroll
    for (int rep = 0; rep < 2; rep++) {
        const int idx = rep * 128 + tid;    // 0..255
        const int row = idx >> 2, seg = idx & 3;
        const uint32_t soff = (uint32_t)(row * (PITCH * 2) + seg * 16);
        const size_t aoff = (size_t)(m0 + row) * H_ + koff + seg * 8;
        const size_t boff = (size_t)(n0 + row) * ldb + k0 + seg * 8;
        cpa16(sb + AHI_O + soff, ah + aoff);
        cpa16(sb + ALO_O + soff, al + aoff);
        cpa16(sb + BHI_O + soff, Bhi + boff);
        cpa16(sb + BLO_O + soff, Blo + boff);
    }
}

template <bool OUTMODE, bool CONCAT>
__device__ __forceinline__ void gemm_wmma(
    char* smem,
    const __nv_bfloat16* __restrict__ Ahi, const __nv_bfloat16* __restrict__ Alo,
    const __nv_bfloat16* __restrict__ A2hi, const __nv_bfloat16* __restrict__ A2lo,
    const __nv_bfloat16* __restrict__ Bhi, const __nv_bfloat16* __restrict__ Blo,
    int ldb, const float* __restrict__ bias, float* __restrict__ C,
    int m0, int n0, int Ktot)
{
    const int tid  = threadIdx.x;
    const int wid  = tid >> 5;
    const int lane = tid & 31;
    const int m0w  = (wid >> 1) * 32;
    const int n0w  = (wid & 1) * 32;
    const uint32_t sb = smem_u32(smem);

    wmma::fragment<wmma::accumulator, 16, 16, 16, float> acc[2][2];
    #pragma unroll
    for (int mi = 0; mi < 2; mi++)
        #pragma unroll
        for (int ni = 0; ni < 2; ni++)
            wmma::fill_fragment(acc[mi][ni], 0.0f);

    const int nchunks = Ktot / 32;

    issue_chunk<CONCAT>(sb, Ahi, Alo, A2hi, A2lo, Bhi, Blo, ldb, m0, n0, 0, tid);
    CP_COMMIT();

    #pragma unroll 1
    for (int it = 0; it < nchunks; ++it) {
        if (it + 1 < nchunks) {
            issue_chunk<CONCAT>(sb + ((it + 1) & 1) * BUF_B,
                                Ahi, Alo, A2hi, A2lo, Bhi, Blo,
                                ldb, m0, n0, (it + 1) * 32, tid);
            CP_COMMIT();
            CP_WAIT1();
        } else {
            CP_WAIT0();
        }
        __syncthreads();

        const char* buf = smem + (it & 1) * BUF_B;
        const __nv_bfloat16* sAhi = reinterpret_cast<const __nv_bfloat16*>(buf + AHI_O);
        const __nv_bfloat16* sAlo = reinterpret_cast<const __nv_bfloat16*>(buf + ALO_O);
        const __nv_bfloat16* sBhi = reinterpret_cast<const __nv_bfloat16*>(buf + BHI_O);
        const __nv_bfloat16* sBlo = reinterpret_cast<const __nv_bfloat16*>(buf + BLO_O);

        #pragma unroll
        for (int kf = 0; kf < 2; kf++) {
            const int ko = kf * 16;
            wmma::fragment<wmma::matrix_a, 16, 16, 16, __nv_bfloat16, wmma::row_major> ahi[2], alo[2];
            wmma::fragment<wmma::matrix_b, 16, 16, 16, __nv_bfloat16, wmma::col_major> bhi[2], blo[2];
            #pragma unroll
            for (int mi = 0; mi < 2; mi++) {
                wmma::load_matrix_sync(ahi[mi], &sAhi[(m0w + 16 * mi) * PITCH + ko], PITCH);
                wmma::load_matrix_sync(alo[mi], &sAlo[(m0w + 16 * mi) * PITCH + ko], PITCH);
            }
            #pragma unroll
            for (int ni = 0; ni < 2; ni++) {
                wmma::load_matrix_sync(bhi[ni], &sBhi[(n0w + 16 * ni) * PITCH + ko], PITCH);
                wmma::load_matrix_sync(blo[ni], &sBlo[(n0w + 16 * ni) * PITCH + ko], PITCH);
            }
            #pragma unroll
            for (int mi = 0; mi < 2; mi++)
                #pragma unroll
                for (int ni = 0; ni < 2; ni++) {
                    wmma::mma_sync(acc[mi][ni], ahi[mi], bhi[ni], acc[mi][ni]);
                    wmma::mma_sync(acc[mi][ni], ahi[mi], blo[ni], acc[mi][ni]);
                    wmma::mma_sync(acc[mi][ni], alo[mi], bhi[ni], acc[mi][ni]);
                }
        }
        __syncthreads();
    }

    if (!OUTMODE) {
        #pragma unroll
        for (int mi = 0; mi < 2; mi++)
            #pragma unroll
            for (int ni = 0; ni < 2; ni++)
                wmma::store_matrix_sync(
                    &C[(size_t)(m0 + m0w + 16 * mi) * H_ + n0 + n0w + 16 * ni],
                    acc[mi][ni], H_, wmma::mem_row_major);
    } else {
        float* stage = reinterpret_cast<float*>(smem) + wid * 32 * 36;
        #pragma unroll
        for (int mi = 0; mi < 2; mi++)
            #pragma unroll
            for (int ni = 0; ni < 2; ni++)
                wmma::store_matrix_sync(&stage[(16 * mi) * 36 + 16 * ni],
                                        acc[mi][ni], 36, wmma::mem_row_major);
        __syncwarp();
        const int m = m0 + m0w + lane;
        float* Crow = C + (size_t)m * H_ + n0 + n0w;
        #pragma unroll
        for (int q = 0; q < 8; q++) {
            const float4 s = *reinterpret_cast<const float4*>(&stage[lane * 36 + q * 4]);
            const float4 bb = *reinterpret_cast<const float4*>(&bias[n0 + n0w + q * 4]);
            float4 o;
            o.x = tanhf(s.x + bb.x); o.y = tanhf(s.y + bb.y);
            o.z = tanhf(s.z + bb.z); o.w = tanhf(s.w + bb.w);
            *reinterpret_cast<float4*>(Crow + q * 4) = o;
        }
    }
}

// proj: grid (8, 48). y<16 -> qs; else hs
__global__ void __launch_bounds__(128) proj_wmma()
{
    __shared__ __align__(16) char smem[SMEM_BYTES];
    const int n0 = blockIdx.x * 64;
    const int my = blockIdx.y;
    if (my < 16)
        gemm_wmma<false, false>(smem, g_qhi, g_qlo, nullptr, nullptr,
                                g_wshi, g_wslo, H_, nullptr, g_qs, my * 64, n0, H_);
    else
        gemm_wmma<false, false>(smem, g_ehi, g_elo, nullptr, nullptr,
                                g_whhi, g_whlo, H_, nullptr, g_hs, (my - 16) * 64, n0, H_);
}

// out: grid (8, 16). out = tanh([ctx|query] @ W_out^T + b), K=1024
__global__ void __launch_bounds__(128) out_wmma(
    const float* __restrict__ b_out, float* __restrict__ out)
{
    __shared__ __align__(16) char smem[SMEM_BYTES];
    gemm_wmma<true, true>(smem, g_chi, g_clo, g_qhi, g_qlo,
                          g_wohi, g_wolo, 2 * H_, b_out, out,
                          blockIdx.y * 64, blockIdx.x * 64, 2 * H_);
}

// ---------------------------------------------------------------------------
// Fused attention, TT=8 (128 blocks, 1/SM), register prefetch of hs chunks,
// ctx emitted directly as bf16 hi/lo.
// ---------------------------------------------------------------------------
#define TT 8
#define SC 16

__global__ void __launch_bounds__(256) attn_kernel(
    const float* __restrict__ enc, const float* __restrict__ v,
    const int* __restrict__ lens)
{
    __shared__ float sh_hs[SC * H_];          // 32 KB (reused for pass-2 combine)
    __shared__ float sh_sc[TT][S_];           // 8 KB
    __shared__ float sh_rsum[TT];

    const int b    = blockIdx.y;
    const int t0   = blockIdx.x * TT;
    const int tid  = threadIdx.x;
    const int lane = tid & 31;
    const int wid  = tid >> 5;                // = t_loc (one warp per t row)

    float qreg[16], vreg[16];
    {
        const float* qrow = g_qs + (size_t)(b * T_ + t0 + wid) * H_;
        #pragma unroll
        for (int j = 0; j < 16; j++) {
            qreg[j] = qrow[lane + 32 * j];
            vreg[j] = v[lane + 32 * j];
        }
    }

    const float* hsb  = g_hs + (size_t)b * S_ * H_;
    const float* encb = enc  + (size_t)b * S_ * H_;

    // ---- Pass 1: scores with register prefetch ----
    float4 r[8];
    #pragma unroll
    for (int q = 0; q < 8; q++)
        r[q] = *reinterpret_cast<const float4*>(&hsb[(q * 256 + tid) * 4]);

    #pragma unroll 1
    for (int it = 0; it < S_ / SC; ++it) {
        #pragma unroll
        for (int q = 0; q < 8; q++)
            *reinterpret_cast<float4*>(&sh_hs[(q * 256 + tid) * 4]) = r[q];
        __syncthreads();

        if (it + 1 < S_ / SC) {
            const float* nxt = &hsb[(size_t)(it + 1) * SC * H_];
            #pragma unroll
            for (int q = 0; q < 8; q++)
                r[q] = *reinterpret_cast<const float4*>(&nxt[(q * 256 + tid) * 4]);
        }

        const int s0 = it * SC;
        #pragma unroll
        for (int i = 0; i < SC; i++) {
            const float* hrow = &sh_hs[i * H_];
            float acc = 0.f;
            #pragma unroll
            for (int j = 0; j < 16; j++) {
                const float x = qreg[j] + hrow[lane + 32 * j];
                float th;
                asm("tanh.approx.f32 %0, %1;" : "=f"(th) : "f"(x));
                acc = fmaf(th, vreg[j], acc);
            }
            acc += __shfl_xor_sync(0xffffffffu, acc, 16);
            acc += __shfl_xor_sync(0xffffffffu, acc, 8);
            acc += __shfl_xor_sync(0xffffffffu, acc, 4);
            acc += __shfl_xor_sync(0xffffffffu, acc, 2);
            acc += __shfl_xor_sync(0xffffffffu, acc, 1);
            if (lane == 0) sh_sc[wid][s0 + i] = acc;
        }
        __syncthreads();
    }

    // ---- Softmax (warp per t row) ----
    const int len = lens[b];
    {
        const int t = wid;
        float vals[S_ / 32];
        float m = -1e30f;
        #pragma unroll
        for (int i = 0; i < S_ / 32; i++) {
            const int s = lane + 32 * i;
            const float sc = (s < len) ? sh_sc[t][s] : -1e30f;
            vals[i] = sc;
            m = fmaxf(m, sc);
        }
        #pragma unroll
        for (int o = 16; o; o >>= 1) m = fmaxf(m, __shfl_xor_sync(0xffffffffu, m, o));
        float sum = 0.f;
        #pragma unroll
        for (int i = 0; i < S_ / 32; i++) {
            const int s = lane + 32 * i;
            const float e = (s < len) ? __expf(vals[i] - m) : 0.f;
            sh_sc[t][s] = e;
            sum += e;
        }
        #pragma unroll
        for (int o = 16; o; o >>= 1) sum += __shfl_xor_sync(0xffffffffu, sum, o);
        if (lane == 0) sh_rsum[t] = 1.0f / sum;
    }
    __syncthreads();

    // ---- Pass 2: context = attn @ enc, emitted as bf16 hi/lo ----
    const int g  = tid >> 7;
    const int c4 = tid & 127;
    float4 acc4[TT];
    #pragma unroll
    for (int t = 0; t < TT; t++) acc4[t] = make_float4(0.f, 0.f, 0.f, 0.f);

    const int sbeg = g * (S_ / 2);
    #pragma unroll 4
    for (int s = sbeg; s < sbeg + S_ / 2; s++) {
        const float4 e4 = *reinterpret_cast<const float4*>(&encb[(size_t)s * H_ + c4 * 4]);
        #pragma unroll
        for (int t = 0; t < TT; t++) {
            const float w = sh_sc[t][s];
            acc4[t].x = fmaf(w, e4.x, acc4[t].x);
            acc4[t].y = fmaf(w, e4.y, acc4[t].y);
            acc4[t].z = fmaf(w, e4.z, acc4[t].z);
            acc4[t].w = fmaf(w, e4.w, acc4[t].w);
        }
    }

    if (g == 0) {
        #pragma unroll
        for (int t = 0; t < TT; t++)
            *reinterpret_cast<float4*>(&sh_hs[(t * 128 + c4) * 4]) = acc4[t];
    }
    __syncthreads();
    if (g == 1) {
        #pragma unroll
        for (int t = 0; t < TT; t++) {
            float4 o = *reinterpret_cast<const float4*>(&sh_hs[(t * 128 + c4) * 4]);
            const float rs = sh_rsum[t];
            o.x = (o.x + acc4[t].x) * rs;
            o.y = (o.y + acc4[t].y) * rs;
            o.z = (o.z + acc4[t].z) * rs;
            o.w = (o.w + acc4[t].w) * rs;
            union { __nv_bfloat16 h[4]; uint2 u; } ph, pl;
            bsplit(o.x, ph.h[0], pl.h[0]); bsplit(o.y, ph.h[1], pl.h[1]);
            bsplit(o.z, ph.h[2], pl.h[2]); bsplit(o.w, ph.h[3], pl.h[3]);
            const size_t off = (size_t)(b * T_ + t0 + t) * H_ + c4 * 4;
            *reinterpret_cast<uint2*>(&g_chi[off]) = ph.u;
            *reinterpret_cast<uint2*>(&g_clo[off]) = pl.u;
        }
    }
}

// ---------------------------------------------------------------------------
extern "C" void kernel_launch(void* const* d_in, const int* in_sizes, int n_in,
                              void* d_out, int out_size)
{
    const float* query = (const float*)d_in[0];
    const float* enc   = (const float*)d_in[1];
    const int*   lens  = (const int*)d_in[2];
    const float* W_s   = (const float*)d_in[3];
    const float* W_h   = (const float*)d_in[4];
    const float* v     = (const float*)d_in[5];
    const float* W_out = (const float*)d_in[6];
    const float* b_out = (const float*)d_in[7];
    float* out = (float*)d_out;

    // split inputs + weights to bf16 hi/lo (655360 float4s)
    convert_kernel<<<2560, 256>>>(query, enc, W_s, W_h, W_out);
    // qs + hs (tensor pipe, cp.async pipelined)
    proj_wmma<<<dim3(8, 48), 128>>>();
    // fused scores/softmax/context (ctx -> bf16 hi/lo)
    attn_kernel<<<dim3(T_ / TT, B_), 256>>>(enc, v, lens);
    // out = tanh([ctx|query] @ W_out^T + b)
    out_wmma<<<dim3(8, 16), 128>>>(b_out, out);
}